// round 12
// baseline (speedup 1.0000x reference)
#include <cuda_runtime.h>
#include <cuda_bf16.h>
#include <cstdint>

#define T_STEPS 10
#define NN      50000
#define NE      800000

#define BN      256
#define NTHR    512
#define NB_SCAN 196     // ceil(50000/256)

#define S0      52      // A0 row stride (48 cols + pad); 52%32=20 -> conflict-free frags
#define S1      68      // A1 row stride (64 cols + pad); 68%32=4  -> conflict-free frags

// ---------------- device scratch ----------------
__device__ float g_deg [NN];
__device__ float g_dinv[NN];
__device__ float g_xs  [NN * 20];
__device__ float g_acc [NN * 20];
__device__ int   g_off [NN];
__device__ int   g_cur [NN];
__device__ int   g_csrc[NE];
__device__ int   g_bsum[256];
__device__ int   g_btop[256];

// ---------------- prep kernels ----------------
__global__ void k_init() {
    int n = blockIdx.x * blockDim.x + threadIdx.x;
    if (n < NN) { g_deg[n] = 1.0f; g_cur[n] = 0; }
}
__global__ void k_count(const int* __restrict__ ei) {
    int e = blockIdx.x * blockDim.x + threadIdx.x;
    if (e < NE) atomicAdd(&g_deg[ei[NE + e]], 1.0f);
}
// block-level exclusive scan of (deg-1); also writes g_dinv
__global__ void k_scan_part() {
    __shared__ int s[256];
    int b = blockIdx.x, tdx = threadIdx.x;
    int n = b * 256 + tdx;
    int v = 0;
    if (n < NN) {
        float dg = g_deg[n];
        g_dinv[n] = rsqrtf(dg);
        v = __float2int_rn(dg) - 1;
    }
    s[tdx] = v;
    __syncthreads();
    for (int d = 1; d < 256; d <<= 1) {
        int tv = (tdx >= d) ? s[tdx - d] : 0;
        __syncthreads();
        s[tdx] += tv;
        __syncthreads();
    }
    if (n < NN) g_off[n] = s[tdx] - v;
    if (tdx == 255) g_bsum[b] = s[255];
}
__global__ void k_scan_top() {
    __shared__ int s[256];
    int tdx = threadIdx.x;
    int v = (tdx < NB_SCAN) ? g_bsum[tdx] : 0;
    s[tdx] = v;
    __syncthreads();
    for (int d = 1; d < 256; d <<= 1) {
        int tv = (tdx >= d) ? s[tdx - d] : 0;
        __syncthreads();
        s[tdx] += tv;
        __syncthreads();
    }
    g_btop[tdx] = s[tdx] - v;
}
__global__ void k_xs(const float* __restrict__ x) {
    int idx = blockIdx.x * blockDim.x + threadIdx.x;
    if (idx < T_STEPS * NN * 2) {
        int n = (idx >> 1) % NN;
        g_xs[n * 20 + (idx / (NN * 2)) * 2 + (idx & 1)] = g_dinv[n] * x[idx];
    }
}
// fill CSR (adds block-prefix at use)
__global__ void k_fill(const int* __restrict__ ei) {
    int e = blockIdx.x * blockDim.x + threadIdx.x;
    if (e < NE) {
        int d = ei[NE + e];
        int p = atomicAdd(&g_cur[d], 1);
        g_csrc[g_off[d] + g_btop[d >> 8] + p] = ei[e];
    }
}
// ---- pull aggregation: one warp per dst, no float atomics ----
__global__ void k_pull() {
    int gw = (blockIdx.x * blockDim.x + threadIdx.x) >> 5;
    int l  = threadIdx.x & 31;
    if (gw >= NN) return;
    int beg = g_off[gw] + g_btop[gw >> 8];
    int num = __float2int_rn(g_deg[gw]) - 1;
    float acc = (l < 20) ? g_xs[gw * 20 + l] : 0.0f;   // self-loop term
    for (int base = 0; base < num; base += 32) {
        int se = (base + l < num) ? g_csrc[beg + base + l] : 0;
        int lim = min(32, num - base);
        for (int j = 0; j < lim; j++) {
            int s = __shfl_sync(0xFFFFFFFFu, se, j);
            if (l < 20) acc += g_xs[s * 20 + l];
        }
    }
    if (l < 20) g_acc[gw * 20 + l] = acc;
}

// ---------------- math helpers ----------------
__device__ __forceinline__ float tanhap(float x) {
    float y;
    asm("tanh.approx.f32 %0, %1;" : "=f"(y) : "f"(x));
    return y;
}
__device__ __forceinline__ float sigf(float x) {
    return fmaf(tanhap(0.5f * x), 0.5f, 0.5f);
}
__device__ __forceinline__ uint32_t tf32b(float x) {
    uint32_t y;
    asm("cvt.rna.tf32.f32 %0, %1;" : "=r"(y) : "f"(x));
    return y;
}
__device__ __forceinline__ void mma_tf32(float d[4], uint32_t a0, uint32_t a1,
                                         uint32_t a2, uint32_t a3,
                                         uint32_t b0, uint32_t b1) {
    asm volatile(
        "mma.sync.aligned.m16n8k8.row.col.f32.tf32.tf32.f32 "
        "{%0,%1,%2,%3}, {%4,%5,%6,%7}, {%8,%9}, {%0,%1,%2,%3};"
        : "+f"(d[0]), "+f"(d[1]), "+f"(d[2]), "+f"(d[3])
        : "r"(a0), "r"(a1), "r"(a2), "r"(a3), "r"(b0), "r"(b1));
}

// smem layout (floats)
#define O_WF0 0                          // [6 kk][16 j][32 lane][2]
#define O_WF1 (O_WF0 + 6 * 16 * 64)      // 6144
#define O_BS0 (O_WF1 + 8 * 16 * 64)      // 14336
#define O_BS1 (O_BS0 + 128)
#define O_OW  (O_BS1 + 128)
#define O_GW  (O_OW + 32)
#define O_GB  (O_GW + 32)
#define O_OUTP (O_GB + 16)               // [256][4]
#define O_XA  (O_OUTP + BN * 4)          // [10][2][256]
#define O_A0  (O_XA + T_STEPS * 2 * BN)
#define O_A1  (O_A0 + BN * S0)
#define SM_FLOATS (O_A1 + BN * S1)
#define SM_BYTES  (SM_FLOATS * 4)        // 206144

__global__ __launch_bounds__(NTHR, 1)
void k_main(const float* __restrict__ wih0, const float* __restrict__ whh0,
            const float* __restrict__ bih0, const float* __restrict__ bhh0,
            const float* __restrict__ wih1, const float* __restrict__ whh1,
            const float* __restrict__ bih1, const float* __restrict__ bhh1,
            const float* __restrict__ gw,   const float* __restrict__ gb,
            const float* __restrict__ ow,   const float* __restrict__ ob,
            float* __restrict__ out) {
    extern __shared__ float sm[];
    uint32_t* wf0 = (uint32_t*)(sm + O_WF0);
    uint32_t* wf1 = (uint32_t*)(sm + O_WF1);
    float* bs0  = sm + O_BS0;
    float* bs1  = sm + O_BS1;
    float* ows  = sm + O_OW;
    float* gws  = sm + O_GW;
    float* gbs  = sm + O_GB;
    float* outp = sm + O_OUTP;
    float* xa   = sm + O_XA;
    uint32_t* A0 = (uint32_t*)(sm + O_A0);
    uint32_t* A1 = (uint32_t*)(sm + O_A1);

    int tid = threadIdx.x;
    int node0 = blockIdx.x * BN;

    // ---- prologue: weights in B-fragment order (tf32) ----
    for (int idx = tid; idx < 6 * 16 * 64; idx += NTHR) {
        int kk = idx >> 10, rem = idx & 1023;
        int j = rem >> 6, ll = (rem >> 1) & 31, half = rem & 1;
        int k = kk * 8 + (ll & 3) + half * 4;
        int c = j * 8 + (ll >> 2);                 // torch gate order i,f,g,o
        float v = (k < 16) ? wih0[c * 16 + k] : whh0[c * 32 + (k - 16)];
        wf0[idx] = tf32b(v);
    }
    for (int idx = tid; idx < 8 * 16 * 64; idx += NTHR) {
        int kk = idx >> 10, rem = idx & 1023;
        int j = rem >> 6, ll = (rem >> 1) & 31, half = rem & 1;
        int k = kk * 8 + (ll & 3) + half * 4;
        int c = j * 8 + (ll >> 2);
        float v = (k < 32) ? wih1[c * 32 + k] : whh1[c * 32 + (k - 32)];
        wf1[idx] = tf32b(v);
    }
    if (tid < 128) { bs0[tid] = bih0[tid] + bhh0[tid]; bs1[tid] = bih1[tid] + bhh1[tid]; }
    if (tid < 32) { ows[tid] = ow[tid]; gws[tid] = gw[tid]; }
    if (tid < 16) gbs[tid] = gb[tid];
    for (int idx = tid; idx < BN * S0; idx += NTHR) A0[idx] = 0u;
    for (int idx = tid; idx < BN * S1; idx += NTHR) A1[idx] = 0u;

    for (int idx = tid; idx < T_STEPS * 2 * BN; idx += NTHR) {
        int nl = idx & (BN - 1);
        int n = node0 + nl;
        if (n >= NN) n = NN - 1;
        xa[idx] = g_acc[n * 20 + (idx >> 8)] * g_dinv[n];
    }
    __syncthreads();

    // ---- warp/lane geometry: 4 row-groups x 4 col-groups ----
    int w = tid >> 5;
    int l = tid & 31;
    int wr = w >> 2;                 // row group: 64 nodes (0..3)
    int wc = w & 3;                  // col group: j in {wc, wc+4, wc+8, wc+12}
    int cb = 2 * (l & 3);
    int u0 = wc * 8 + cb;            // this thread's units u0, u0+1 (per gate type g)
    int rbase = wr * 64 + (l >> 2);  // node row base (+16*mt, +8*rho)

    float c0[16], c1[16];
#pragma unroll
    for (int i = 0; i < 16; i++) { c0[i] = 0.0f; c1[i] = 0.0f; }
    float obv = ob[0];

    for (int t = 0; t < T_STEPS; t++) {
        // ---- GCN ReLU features (tf32) into A0 cols 0..15 ----
        {
            int nl = tid >> 1, f0 = (tid & 1) * 8;
            float x0v = xa[t * 2 * BN + nl];
            float x1v = xa[t * 2 * BN + BN + nl];
            uint32_t fv[8];
#pragma unroll
            for (int f = 0; f < 8; f++) {
                float v = fmaf(x0v, gws[(f0 + f) * 2],
                          fmaf(x1v, gws[(f0 + f) * 2 + 1], gbs[f0 + f]));
                fv[f] = tf32b(fmaxf(v, 0.0f));
            }
            uint32_t* p = A0 + nl * S0 + f0;
            *(uint4*)(p)     = make_uint4(fv[0], fv[1], fv[2], fv[3]);
            *(uint4*)(p + 4) = make_uint4(fv[4], fv[5], fv[6], fv[7]);
        }
        __syncthreads();   // B1

        // ---- layer0 GEMM: 64 nodes x 32 gates per warp, K=48 ----
        float d[4][4][4];
#pragma unroll
        for (int mt = 0; mt < 4; mt++)
#pragma unroll
            for (int g = 0; g < 4; g++) {
                float b0v = bs0[g * 32 + u0], b1v = bs0[g * 32 + u0 + 1];
                d[mt][g][0] = b0v; d[mt][g][1] = b1v; d[mt][g][2] = b0v; d[mt][g][3] = b1v;
            }
#pragma unroll
        for (int kk = 0; kk < 6; kk++) {
            uint32_t a0[4], a1[4], a2[4], a3[4];
#pragma unroll
            for (int mt = 0; mt < 4; mt++) {
                int ab = (rbase + mt * 16) * S0 + kk * 8 + (l & 3);
                a0[mt] = A0[ab];
                a1[mt] = A0[ab + 8 * S0];
                a2[mt] = A0[ab + 4];
                a3[mt] = A0[ab + 8 * S0 + 4];
            }
#pragma unroll
            for (int g = 0; g < 4; g++) {
                uint2 b = ((const uint2*)wf0)[(kk * 16 + wc + 4 * g) * 32 + l];
#pragma unroll
                for (int mt = 0; mt < 4; mt++)
                    mma_tf32(d[mt][g], a0[mt], a1[mt], a2[mt], a3[mt], b.x, b.y);
            }
        }
        __syncthreads();   // B2

        // ---- layer0 activations (approx); h0 -> A0[16..48], A1[0..32] ----
#pragma unroll
        for (int mt = 0; mt < 4; mt++)
#pragma unroll
            for (int rho = 0; rho < 2; rho++)
#pragma unroll
                for (int p = 0; p < 2; p++) {
                    int q = 2 * rho + p;
                    int ci = (mt * 2 + rho) * 2 + p;
                    float gi = d[mt][0][q], gf = d[mt][1][q];
                    float gg = d[mt][2][q], go = d[mt][3][q];
                    float cc = sigf(gf) * c0[ci] + sigf(gi) * tanhap(gg);
                    c0[ci] = cc;
                    float h = sigf(go) * tanhap(cc);
                    int u = u0 + p;
                    int node = rbase + mt * 16 + 8 * rho;
                    uint32_t hb = tf32b(h);
                    A0[node * S0 + 16 + u] = hb;
                    A1[node * S1 + u]      = hb;
                }
        __syncthreads();   // B3

        // ---- layer1 GEMM: K=64 ----
#pragma unroll
        for (int mt = 0; mt < 4; mt++)
#pragma unroll
            for (int g = 0; g < 4; g++) {
                float b0v = bs1[g * 32 + u0], b1v = bs1[g * 32 + u0 + 1];
                d[mt][g][0] = b0v; d[mt][g][1] = b1v; d[mt][g][2] = b0v; d[mt][g][3] = b1v;
            }
#pragma unroll
        for (int kk = 0; kk < 8; kk++) {
            uint32_t a0[4], a1[4], a2[4], a3[4];
#pragma unroll
            for (int mt = 0; mt < 4; mt++) {
                int ab = (rbase + mt * 16) * S1 + kk * 8 + (l & 3);
                a0[mt] = A1[ab];
                a1[mt] = A1[ab + 8 * S1];
                a2[mt] = A1[ab + 4];
                a3[mt] = A1[ab + 8 * S1 + 4];
            }
#pragma unroll
            for (int g = 0; g < 4; g++) {
                uint2 b = ((const uint2*)wf1)[(kk * 16 + wc + 4 * g) * 32 + l];
#pragma unroll
                for (int mt = 0; mt < 4; mt++)
                    mma_tf32(d[mt][g], a0[mt], a1[mt], a2[mt], a3[mt], b.x, b.y);
            }
        }
        __syncthreads();   // B4

        // ---- layer1 activations (approx); h1 -> A1[32..64]; output partials ----
#pragma unroll
        for (int mt = 0; mt < 4; mt++)
#pragma unroll
            for (int rho = 0; rho < 2; rho++) {
                float po = 0.0f;
#pragma unroll
                for (int p = 0; p < 2; p++) {
                    int q = 2 * rho + p;
                    int ci = (mt * 2 + rho) * 2 + p;
                    float gi = d[mt][0][q], gf = d[mt][1][q];
                    float gg = d[mt][2][q], go = d[mt][3][q];
                    float cc = sigf(gf) * c1[ci] + sigf(gi) * tanhap(gg);
                    c1[ci] = cc;
                    float h = sigf(go) * tanhap(cc);
                    int u = u0 + p;
                    int node = rbase + mt * 16 + 8 * rho;
                    A1[node * S1 + 32 + u] = tf32b(h);
                    po = fmaf(h, ows[u], po);
                }
                // sum over the 4 lanes sharing this node (units wc*8..wc*8+7)
                po += __shfl_xor_sync(0xFFFFFFFFu, po, 1);
                po += __shfl_xor_sync(0xFFFFFFFFu, po, 2);
                if ((l & 3) == 0) {
                    int node = rbase + mt * 16 + 8 * rho;
                    outp[node * 4 + wc] = po;
                }
            }
        __syncthreads();   // B5

        if (tid < BN) {
            int n = node0 + tid;
            if (n < NN) {
                out[t * NN + n] = obv + outp[tid * 4] + outp[tid * 4 + 1]
                                      + outp[tid * 4 + 2] + outp[tid * 4 + 3];
            }
        }
        // outp reads finish before next t's B4 rewrites; A-buffer reuse guarded by B1/B2
    }
}

// ---------------- launcher ----------------
extern "C" void kernel_launch(void* const* d_in, const int* in_sizes, int n_in,
                              void* d_out, int out_size) {
    const float* x    = (const float*)d_in[0];
    const int*   ei   = (const int*)  d_in[1];
    const float* gw   = (const float*)d_in[2];
    const float* gb   = (const float*)d_in[3];
    const float* wih0 = (const float*)d_in[4];
    const float* whh0 = (const float*)d_in[5];
    const float* bih0 = (const float*)d_in[6];
    const float* bhh0 = (const float*)d_in[7];
    const float* wih1 = (const float*)d_in[8];
    const float* whh1 = (const float*)d_in[9];
    const float* bih1 = (const float*)d_in[10];
    const float* bhh1 = (const float*)d_in[11];
    const float* ow   = (const float*)d_in[12];
    const float* ob   = (const float*)d_in[13];
    float* out = (float*)d_out;

    cudaFuncSetAttribute(k_main, cudaFuncAttributeMaxDynamicSharedMemorySize, SM_BYTES);

    k_init     <<<(NN + 255) / 256, 256>>>();
    k_count    <<<(NE + 255) / 256, 256>>>(ei);
    k_scan_part<<<NB_SCAN, 256>>>();
    k_xs       <<<(T_STEPS * NN * 2 + 255) / 256, 256>>>(x);
    k_scan_top <<<1, 256>>>();
    k_fill     <<<(NE + 255) / 256, 256>>>(ei);
    k_pull     <<<(NN * 32 + 255) / 256, 256>>>();
    k_main     <<<(NN + BN - 1) / BN, NTHR, SM_BYTES>>>(
        wih0, whh0, bih0, bhh0, wih1, whh1, bih1, bhh1, gw, gb, ow, ob, out);
}

// round 13
// speedup vs baseline: 1.2178x; 1.2178x over previous
#include <cuda_runtime.h>
#include <cuda_bf16.h>
#include <cstdint>

#define T_STEPS 10
#define NN      50000
#define NE      800000

#define BN      128
#define NTHR    512
#define NB_SCAN 196     // ceil(50000/256)

#define S0      52      // A0 row stride (48 cols + pad); 52%32=20 -> conflict-free frags
#define S1      68      // A1 row stride (64 cols + pad); 68%32=4  -> conflict-free frags

// ---------------- device scratch ----------------
__device__ float g_deg [NN];
__device__ float g_dinv[NN];
__device__ float g_xs  [NN * 20];
__device__ float g_acc [NN * 20];
__device__ int   g_off [NN];
__device__ int   g_cur [NN];
__device__ int   g_csrc[NE];
__device__ int   g_bsum[256];
__device__ int   g_btop[256];

// ---------------- prep kernels ----------------
__global__ void k_init() {
    int n = blockIdx.x * blockDim.x + threadIdx.x;
    if (n < NN) { g_deg[n] = 1.0f; g_cur[n] = 0; }
}
__global__ void k_count(const int* __restrict__ ei) {
    int e = blockIdx.x * blockDim.x + threadIdx.x;
    if (e < NE) atomicAdd(&g_deg[ei[NE + e]], 1.0f);
}
// block-level exclusive scan of (deg-1); also writes g_dinv
__global__ void k_scan_part() {
    __shared__ int s[256];
    int b = blockIdx.x, tdx = threadIdx.x;
    int n = b * 256 + tdx;
    int v = 0;
    if (n < NN) {
        float dg = g_deg[n];
        g_dinv[n] = rsqrtf(dg);
        v = __float2int_rn(dg) - 1;
    }
    s[tdx] = v;
    __syncthreads();
    for (int d = 1; d < 256; d <<= 1) {
        int tv = (tdx >= d) ? s[tdx - d] : 0;
        __syncthreads();
        s[tdx] += tv;
        __syncthreads();
    }
    if (n < NN) g_off[n] = s[tdx] - v;
    if (tdx == 255) g_bsum[b] = s[255];
}
__global__ void k_scan_top() {
    __shared__ int s[256];
    int tdx = threadIdx.x;
    int v = (tdx < NB_SCAN) ? g_bsum[tdx] : 0;
    s[tdx] = v;
    __syncthreads();
    for (int d = 1; d < 256; d <<= 1) {
        int tv = (tdx >= d) ? s[tdx - d] : 0;
        __syncthreads();
        s[tdx] += tv;
        __syncthreads();
    }
    g_btop[tdx] = s[tdx] - v;
}
__global__ void k_xs(const float* __restrict__ x) {
    int idx = blockIdx.x * blockDim.x + threadIdx.x;
    if (idx < T_STEPS * NN * 2) {
        int n = (idx >> 1) % NN;
        g_xs[n * 20 + (idx / (NN * 2)) * 2 + (idx & 1)] = g_dinv[n] * x[idx];
    }
}
// fill CSR (adds block-prefix at use)
__global__ void k_fill(const int* __restrict__ ei) {
    int e = blockIdx.x * blockDim.x + threadIdx.x;
    if (e < NE) {
        int d = ei[NE + e];
        int p = atomicAdd(&g_cur[d], 1);
        g_csrc[g_off[d] + g_btop[d >> 8] + p] = ei[e];
    }
}
// ---- pull aggregation: one warp per dst, no float atomics ----
__global__ void k_pull() {
    int gw = (blockIdx.x * blockDim.x + threadIdx.x) >> 5;
    int l  = threadIdx.x & 31;
    if (gw >= NN) return;
    int beg = g_off[gw] + g_btop[gw >> 8];
    int num = __float2int_rn(g_deg[gw]) - 1;
    float acc = (l < 20) ? g_xs[gw * 20 + l] : 0.0f;   // self-loop term
    for (int base = 0; base < num; base += 32) {
        int se = (base + l < num) ? g_csrc[beg + base + l] : 0;
        int lim = min(32, num - base);
        for (int j = 0; j < lim; j++) {
            int s = __shfl_sync(0xFFFFFFFFu, se, j);
            if (l < 20) acc += g_xs[s * 20 + l];
        }
    }
    if (l < 20) g_acc[gw * 20 + l] = acc;
}

// ---------------- math helpers ----------------
__device__ __forceinline__ float tanhap(float x) {
    float y;
    asm("tanh.approx.f32 %0, %1;" : "=f"(y) : "f"(x));
    return y;
}
__device__ __forceinline__ float sigf(float x) {
    return fmaf(tanhap(0.5f * x), 0.5f, 0.5f);
}
__device__ __forceinline__ uint32_t tf32b(float x) {
    uint32_t y;
    asm("cvt.rna.tf32.f32 %0, %1;" : "=r"(y) : "f"(x));
    return y;
}
__device__ __forceinline__ void mma_tf32(float d[4], uint32_t a0, uint32_t a1,
                                         uint32_t a2, uint32_t a3,
                                         uint32_t b0, uint32_t b1) {
    asm volatile(
        "mma.sync.aligned.m16n8k8.row.col.f32.tf32.tf32.f32 "
        "{%0,%1,%2,%3}, {%4,%5,%6,%7}, {%8,%9}, {%0,%1,%2,%3};"
        : "+f"(d[0]), "+f"(d[1]), "+f"(d[2]), "+f"(d[3])
        : "r"(a0), "r"(a1), "r"(a2), "r"(a3), "r"(b0), "r"(b1));
}

// smem layout (floats)
#define O_WF0 0                          // [6 kk][16 j][32 lane][2]
#define O_WF1 (O_WF0 + 6 * 16 * 64)      // 6144
#define O_BS0 (O_WF1 + 8 * 16 * 64)      // 14336
#define O_BS1 (O_BS0 + 128)
#define O_OW  (O_BS1 + 128)
#define O_GW  (O_OW + 32)
#define O_GB  (O_GW + 32)
#define O_OUTP (O_GB + 16)               // [128][4]
#define O_XA  (O_OUTP + BN * 4)          // [10][2][128]
#define O_A0  (O_XA + T_STEPS * 2 * BN)
#define O_A1  (O_A0 + BN * S0)
#define SM_FLOATS (O_A1 + BN * S1)
#define SM_BYTES  (SM_FLOATS * 4)        // 132416

__global__ __launch_bounds__(NTHR, 1)
void k_main(const float* __restrict__ wih0, const float* __restrict__ whh0,
            const float* __restrict__ bih0, const float* __restrict__ bhh0,
            const float* __restrict__ wih1, const float* __restrict__ whh1,
            const float* __restrict__ bih1, const float* __restrict__ bhh1,
            const float* __restrict__ gw,   const float* __restrict__ gb,
            const float* __restrict__ ow,   const float* __restrict__ ob,
            float* __restrict__ out) {
    extern __shared__ float sm[];
    uint32_t* wf0 = (uint32_t*)(sm + O_WF0);
    uint32_t* wf1 = (uint32_t*)(sm + O_WF1);
    float* bs0  = sm + O_BS0;
    float* bs1  = sm + O_BS1;
    float* ows  = sm + O_OW;
    float* gws  = sm + O_GW;
    float* gbs  = sm + O_GB;
    float* outp = sm + O_OUTP;
    float* xa   = sm + O_XA;
    uint32_t* A0 = (uint32_t*)(sm + O_A0);
    uint32_t* A1 = (uint32_t*)(sm + O_A1);

    int tid = threadIdx.x;
    int node0 = blockIdx.x * BN;

    // ---- prologue: weights in B-fragment order (tf32) ----
    for (int idx = tid; idx < 6 * 16 * 64; idx += NTHR) {
        int kk = idx >> 10, rem = idx & 1023;
        int j = rem >> 6, ll = (rem >> 1) & 31, half = rem & 1;
        int k = kk * 8 + (ll & 3) + half * 4;
        int c = j * 8 + (ll >> 2);                 // torch gate order i,f,g,o
        float v = (k < 16) ? wih0[c * 16 + k] : whh0[c * 32 + (k - 16)];
        wf0[idx] = tf32b(v);
    }
    for (int idx = tid; idx < 8 * 16 * 64; idx += NTHR) {
        int kk = idx >> 10, rem = idx & 1023;
        int j = rem >> 6, ll = (rem >> 1) & 31, half = rem & 1;
        int k = kk * 8 + (ll & 3) + half * 4;
        int c = j * 8 + (ll >> 2);
        float v = (k < 32) ? wih1[c * 32 + k] : whh1[c * 32 + (k - 32)];
        wf1[idx] = tf32b(v);
    }
    if (tid < 128) { bs0[tid] = bih0[tid] + bhh0[tid]; bs1[tid] = bih1[tid] + bhh1[tid]; }
    if (tid < 32) { ows[tid] = ow[tid]; gws[tid] = gw[tid]; }
    if (tid < 16) gbs[tid] = gb[tid];
    for (int idx = tid; idx < BN * S0; idx += NTHR) A0[idx] = 0u;
    for (int idx = tid; idx < BN * S1; idx += NTHR) A1[idx] = 0u;

    for (int idx = tid; idx < T_STEPS * 2 * BN; idx += NTHR) {
        int nl = idx & (BN - 1);
        int n = node0 + nl;
        if (n >= NN) n = NN - 1;
        xa[idx] = g_acc[n * 20 + (idx >> 7)] * g_dinv[n];
    }
    __syncthreads();

    // ---- warp/lane geometry: 4 row-groups (32 nodes, 2 m-tiles) x 4 col-groups ----
    int w = tid >> 5;
    int l = tid & 31;
    int wr = w >> 2;                 // row group 0..3: nodes wr*32 .. wr*32+31
    int wc = w & 3;                  // col group: j in {wc, wc+4, wc+8, wc+12}
    int cb = 2 * (l & 3);
    int u0 = wc * 8 + cb;            // this thread's units u0, u0+1 (per gate type g)
    int rbase = wr * 32 + (l >> 2);  // node row base (+16*mt, +8*rho)

    float c0[8], c1[8];
#pragma unroll
    for (int i = 0; i < 8; i++) { c0[i] = 0.0f; c1[i] = 0.0f; }
    float obv = ob[0];

    for (int t = 0; t < T_STEPS; t++) {
        // ---- GCN ReLU features (tf32) into A0 cols 0..15 (512 thr: 4 feats each) ----
        {
            int nl = tid >> 2, f0 = (tid & 3) * 4;
            float x0v = xa[t * 2 * BN + nl];
            float x1v = xa[t * 2 * BN + BN + nl];
            uint32_t fv[4];
#pragma unroll
            for (int f = 0; f < 4; f++) {
                float v = fmaf(x0v, gws[(f0 + f) * 2],
                          fmaf(x1v, gws[(f0 + f) * 2 + 1], gbs[f0 + f]));
                fv[f] = tf32b(fmaxf(v, 0.0f));
            }
            *(uint4*)(A0 + nl * S0 + f0) = make_uint4(fv[0], fv[1], fv[2], fv[3]);
        }
        __syncthreads();   // B1

        // ---- layer0 GEMM: 32 nodes x 32 gates per warp, K=48 ----
        float d[2][4][4];
#pragma unroll
        for (int mt = 0; mt < 2; mt++)
#pragma unroll
            for (int g = 0; g < 4; g++) {
                float b0v = bs0[g * 32 + u0], b1v = bs0[g * 32 + u0 + 1];
                d[mt][g][0] = b0v; d[mt][g][1] = b1v; d[mt][g][2] = b0v; d[mt][g][3] = b1v;
            }
#pragma unroll
        for (int kk = 0; kk < 6; kk++) {
            uint32_t a0[2], a1[2], a2[2], a3[2];
#pragma unroll
            for (int mt = 0; mt < 2; mt++) {
                int ab = (rbase + mt * 16) * S0 + kk * 8 + (l & 3);
                a0[mt] = A0[ab];
                a1[mt] = A0[ab + 8 * S0];
                a2[mt] = A0[ab + 4];
                a3[mt] = A0[ab + 8 * S0 + 4];
            }
#pragma unroll
            for (int g = 0; g < 4; g++) {
                uint2 b = ((const uint2*)wf0)[(kk * 16 + wc + 4 * g) * 32 + l];
#pragma unroll
                for (int mt = 0; mt < 2; mt++)
                    mma_tf32(d[mt][g], a0[mt], a1[mt], a2[mt], a3[mt], b.x, b.y);
            }
        }
        __syncthreads();   // B2

        // ---- layer0 activations (approx); h0 -> A0[16..48], A1[0..32] ----
#pragma unroll
        for (int mt = 0; mt < 2; mt++)
#pragma unroll
            for (int rho = 0; rho < 2; rho++)
#pragma unroll
                for (int p = 0; p < 2; p++) {
                    int q = 2 * rho + p;
                    int ci = (mt * 2 + rho) * 2 + p;
                    float gi = d[mt][0][q], gf = d[mt][1][q];
                    float gg = d[mt][2][q], go = d[mt][3][q];
                    float cc = sigf(gf) * c0[ci] + sigf(gi) * tanhap(gg);
                    c0[ci] = cc;
                    float h = sigf(go) * tanhap(cc);
                    int u = u0 + p;
                    int node = rbase + mt * 16 + 8 * rho;
                    uint32_t hb = tf32b(h);
                    A0[node * S0 + 16 + u] = hb;
                    A1[node * S1 + u]      = hb;
                }
        __syncthreads();   // B3

        // ---- layer1 GEMM: K=64 ----
#pragma unroll
        for (int mt = 0; mt < 2; mt++)
#pragma unroll
            for (int g = 0; g < 4; g++) {
                float b0v = bs1[g * 32 + u0], b1v = bs1[g * 32 + u0 + 1];
                d[mt][g][0] = b0v; d[mt][g][1] = b1v; d[mt][g][2] = b0v; d[mt][g][3] = b1v;
            }
#pragma unroll
        for (int kk = 0; kk < 8; kk++) {
            uint32_t a0[2], a1[2], a2[2], a3[2];
#pragma unroll
            for (int mt = 0; mt < 2; mt++) {
                int ab = (rbase + mt * 16) * S1 + kk * 8 + (l & 3);
                a0[mt] = A1[ab];
                a1[mt] = A1[ab + 8 * S1];
                a2[mt] = A1[ab + 4];
                a3[mt] = A1[ab + 8 * S1 + 4];
            }
#pragma unroll
            for (int g = 0; g < 4; g++) {
                uint2 b = ((const uint2*)wf1)[(kk * 16 + wc + 4 * g) * 32 + l];
#pragma unroll
                for (int mt = 0; mt < 2; mt++)
                    mma_tf32(d[mt][g], a0[mt], a1[mt], a2[mt], a3[mt], b.x, b.y);
            }
        }
        __syncthreads();   // B4

        // ---- layer1 activations (approx); h1 -> A1[32..64]; output partials ----
#pragma unroll
        for (int mt = 0; mt < 2; mt++)
#pragma unroll
            for (int rho = 0; rho < 2; rho++) {
                float po = 0.0f;
#pragma unroll
                for (int p = 0; p < 2; p++) {
                    int q = 2 * rho + p;
                    int ci = (mt * 2 + rho) * 2 + p;
                    float gi = d[mt][0][q], gf = d[mt][1][q];
                    float gg = d[mt][2][q], go = d[mt][3][q];
                    float cc = sigf(gf) * c1[ci] + sigf(gi) * tanhap(gg);
                    c1[ci] = cc;
                    float h = sigf(go) * tanhap(cc);
                    int u = u0 + p;
                    int node = rbase + mt * 16 + 8 * rho;
                    A1[node * S1 + 32 + u] = tf32b(h);
                    po = fmaf(h, ows[u], po);
                }
                // sum over the 4 lanes sharing this node (units wc*8..wc*8+7)
                po += __shfl_xor_sync(0xFFFFFFFFu, po, 1);
                po += __shfl_xor_sync(0xFFFFFFFFu, po, 2);
                if ((l & 3) == 0) {
                    int node = rbase + mt * 16 + 8 * rho;
                    outp[node * 4 + wc] = po;
                }
            }
        __syncthreads();   // B5

        if (tid < BN) {
            int n = node0 + tid;
            if (n < NN) {
                out[t * NN + n] = obv + outp[tid * 4] + outp[tid * 4 + 1]
                                      + outp[tid * 4 + 2] + outp[tid * 4 + 3];
            }
        }
        // outp reads finish before next t's B4 rewrites; A-buffer reuse guarded by B1/B2
    }
}

// ---------------- launcher ----------------
extern "C" void kernel_launch(void* const* d_in, const int* in_sizes, int n_in,
                              void* d_out, int out_size) {
    const float* x    = (const float*)d_in[0];
    const int*   ei   = (const int*)  d_in[1];
    const float* gw   = (const float*)d_in[2];
    const float* gb   = (const float*)d_in[3];
    const float* wih0 = (const float*)d_in[4];
    const float* whh0 = (const float*)d_in[5];
    const float* bih0 = (const float*)d_in[6];
    const float* bhh0 = (const float*)d_in[7];
    const float* wih1 = (const float*)d_in[8];
    const float* whh1 = (const float*)d_in[9];
    const float* bih1 = (const float*)d_in[10];
    const float* bhh1 = (const float*)d_in[11];
    const float* ow   = (const float*)d_in[12];
    const float* ob   = (const float*)d_in[13];
    float* out = (float*)d_out;

    cudaFuncSetAttribute(k_main, cudaFuncAttributeMaxDynamicSharedMemorySize, SM_BYTES);

    k_init     <<<(NN + 255) / 256, 256>>>();
    k_count    <<<(NE + 255) / 256, 256>>>(ei);
    k_scan_part<<<NB_SCAN, 256>>>();
    k_xs       <<<(T_STEPS * NN * 2 + 255) / 256, 256>>>(x);
    k_scan_top <<<1, 256>>>();
    k_fill     <<<(NE + 255) / 256, 256>>>(ei);
    k_pull     <<<(NN * 32 + 255) / 256, 256>>>();
    k_main     <<<(NN + BN - 1) / BN, NTHR, SM_BYTES>>>(
        wih0, whh0, bih0, bhh0, wih1, whh1, bih1, bhh1, gw, gb, ow, ob, out);
}

// round 14
// speedup vs baseline: 1.3655x; 1.1212x over previous
#include <cuda_runtime.h>
#include <cuda_bf16.h>
#include <cstdint>

#define T_STEPS 10
#define NN      50000
#define NE      800000

#define BN      64
#define NTHR    256
#define NB_SCAN 196     // ceil(50000/256)

#define S0      20      // A0 row stride (16 feat cols + pad); frag reads hit all 32 banks
#define S1      68      // A1 row stride (64 cols + pad); 68%32=4 -> conflict-free frags

// ---------------- device scratch ----------------
__device__ float g_deg [NN];
__device__ float g_dinv[NN];
__device__ float g_xs  [NN * 20];
__device__ float g_acc [NN * 20];
__device__ int   g_off [NN];
__device__ int   g_cur [NN];
__device__ int   g_csrc[NE];
__device__ int   g_bsum[256];
__device__ int   g_btop[256];

// ---------------- prep kernels ----------------
__global__ void k_init() {
    int n = blockIdx.x * blockDim.x + threadIdx.x;
    if (n < NN) { g_deg[n] = 1.0f; g_cur[n] = 0; }
}
__global__ void k_count(const int* __restrict__ ei) {
    int e = blockIdx.x * blockDim.x + threadIdx.x;
    if (e < NE) atomicAdd(&g_deg[ei[NE + e]], 1.0f);
}
// block-level exclusive scan of (deg-1); also writes g_dinv
__global__ void k_scan_part() {
    __shared__ int s[256];
    int b = blockIdx.x, tdx = threadIdx.x;
    int n = b * 256 + tdx;
    int v = 0;
    if (n < NN) {
        float dg = g_deg[n];
        g_dinv[n] = rsqrtf(dg);
        v = __float2int_rn(dg) - 1;
    }
    s[tdx] = v;
    __syncthreads();
    for (int d = 1; d < 256; d <<= 1) {
        int tv = (tdx >= d) ? s[tdx - d] : 0;
        __syncthreads();
        s[tdx] += tv;
        __syncthreads();
    }
    if (n < NN) g_off[n] = s[tdx] - v;
    if (tdx == 255) g_bsum[b] = s[255];
}
__global__ void k_scan_top() {
    __shared__ int s[256];
    int tdx = threadIdx.x;
    int v = (tdx < NB_SCAN) ? g_bsum[tdx] : 0;
    s[tdx] = v;
    __syncthreads();
    for (int d = 1; d < 256; d <<= 1) {
        int tv = (tdx >= d) ? s[tdx - d] : 0;
        __syncthreads();
        s[tdx] += tv;
        __syncthreads();
    }
    g_btop[tdx] = s[tdx] - v;
}
__global__ void k_xs(const float* __restrict__ x) {
    int idx = blockIdx.x * blockDim.x + threadIdx.x;
    if (idx < T_STEPS * NN * 2) {
        int n = (idx >> 1) % NN;
        g_xs[n * 20 + (idx / (NN * 2)) * 2 + (idx & 1)] = g_dinv[n] * x[idx];
    }
}
// fill CSR (adds block-prefix at use)
__global__ void k_fill(const int* __restrict__ ei) {
    int e = blockIdx.x * blockDim.x + threadIdx.x;
    if (e < NE) {
        int d = ei[NE + e];
        int p = atomicAdd(&g_cur[d], 1);
        g_csrc[g_off[d] + g_btop[d >> 8] + p] = ei[e];
    }
}
// ---- pull aggregation: one warp per dst; final dinv[dst] scaling folded in ----
__global__ void k_pull() {
    int gw = (blockIdx.x * blockDim.x + threadIdx.x) >> 5;
    int l  = threadIdx.x & 31;
    if (gw >= NN) return;
    int beg = g_off[gw] + g_btop[gw >> 8];
    int num = __float2int_rn(g_deg[gw]) - 1;
    float acc = (l < 20) ? g_xs[gw * 20 + l] : 0.0f;   // self-loop term
    for (int base = 0; base < num; base += 32) {
        int se = (base + l < num) ? g_csrc[beg + base + l] : 0;
        int lim = min(32, num - base);
        for (int j = 0; j < lim; j++) {
            int s = __shfl_sync(0xFFFFFFFFu, se, j);
            if (l < 20) acc += g_xs[s * 20 + l];
        }
    }
    if (l < 20) g_acc[gw * 20 + l] = acc * g_dinv[gw];
}

// ---------------- math helpers ----------------
__device__ __forceinline__ float tanhap(float x) {
    float y;
    asm("tanh.approx.f32 %0, %1;" : "=f"(y) : "f"(x));
    return y;
}
__device__ __forceinline__ float sigf(float x) {
    return fmaf(tanhap(0.5f * x), 0.5f, 0.5f);
}
__device__ __forceinline__ uint32_t tf32b(float x) {
    uint32_t y;
    asm("cvt.rna.tf32.f32 %0, %1;" : "=r"(y) : "f"(x));
    return y;
}
__device__ __forceinline__ void mma_tf32(float d[4], uint32_t a0, uint32_t a1,
                                         uint32_t a2, uint32_t a3,
                                         uint32_t b0, uint32_t b1) {
    asm volatile(
        "mma.sync.aligned.m16n8k8.row.col.f32.tf32.tf32.f32 "
        "{%0,%1,%2,%3}, {%4,%5,%6,%7}, {%8,%9}, {%0,%1,%2,%3};"
        : "+f"(d[0]), "+f"(d[1]), "+f"(d[2]), "+f"(d[3])
        : "r"(a0), "r"(a1), "r"(a2), "r"(a3), "r"(b0), "r"(b1));
}

// smem layout (floats)
#define O_WF0 0                          // [6 kk][16 j][32 lane][2]
#define O_WF1 (O_WF0 + 6 * 16 * 64)      // 6144
#define O_BS0 (O_WF1 + 8 * 16 * 64)      // 14336
#define O_BS1 (O_BS0 + 128)
#define O_OW  (O_BS1 + 128)
#define O_GW  (O_OW + 32)
#define O_GB  (O_GW + 32)
#define O_OUTP (O_GB + 16)               // [64][4]
#define O_XA  (O_OUTP + BN * 4)          // [10][2][64]
#define O_A0  (O_XA + T_STEPS * 2 * BN)  // [64][S0] feats only
#define O_A1  (O_A0 + BN * S0)           // [64][S1]: cols 0..31 h0, 32..63 h1
#define SM_FLOATS (O_A1 + BN * S1)       // 21840
#define SM_BYTES  (SM_FLOATS * 4)        // 87360 -> 2 CTAs/SM

__global__ __launch_bounds__(NTHR, 2)
void k_main(const float* __restrict__ wih0, const float* __restrict__ whh0,
            const float* __restrict__ bih0, const float* __restrict__ bhh0,
            const float* __restrict__ wih1, const float* __restrict__ whh1,
            const float* __restrict__ bih1, const float* __restrict__ bhh1,
            const float* __restrict__ gw,   const float* __restrict__ gb,
            const float* __restrict__ ow,   const float* __restrict__ ob,
            float* __restrict__ out) {
    extern __shared__ float sm[];
    uint32_t* wf0 = (uint32_t*)(sm + O_WF0);
    uint32_t* wf1 = (uint32_t*)(sm + O_WF1);
    float* bs0  = sm + O_BS0;
    float* bs1  = sm + O_BS1;
    float* ows  = sm + O_OW;
    float* gws  = sm + O_GW;
    float* gbs  = sm + O_GB;
    float* outp = sm + O_OUTP;
    float* xa   = sm + O_XA;
    uint32_t* A0 = (uint32_t*)(sm + O_A0);
    uint32_t* A1 = (uint32_t*)(sm + O_A1);

    int tid = threadIdx.x;
    int node0 = blockIdx.x * BN;

    // ---- prologue: weights in B-fragment order (tf32) ----
    for (int idx = tid; idx < 6 * 16 * 64; idx += NTHR) {
        int kk = idx >> 10, rem = idx & 1023;
        int j = rem >> 6, ll = (rem >> 1) & 31, half = rem & 1;
        int k = kk * 8 + (ll & 3) + half * 4;
        int c = j * 8 + (ll >> 2);                 // torch gate order i,f,g,o
        float v = (k < 16) ? wih0[c * 16 + k] : whh0[c * 32 + (k - 16)];
        wf0[idx] = tf32b(v);
    }
    for (int idx = tid; idx < 8 * 16 * 64; idx += NTHR) {
        int kk = idx >> 10, rem = idx & 1023;
        int j = rem >> 6, ll = (rem >> 1) & 31, half = rem & 1;
        int k = kk * 8 + (ll & 3) + half * 4;
        int c = j * 8 + (ll >> 2);
        float v = (k < 32) ? wih1[c * 32 + k] : whh1[c * 32 + (k - 32)];
        wf1[idx] = tf32b(v);
    }
    if (tid < 128) { bs0[tid] = bih0[tid] + bhh0[tid]; bs1[tid] = bih1[tid] + bhh1[tid]; }
    if (tid < 32) { ows[tid] = ow[tid]; gws[tid] = gw[tid]; }
    if (tid < 16) gbs[tid] = gb[tid];
    for (int idx = tid; idx < BN * S0; idx += NTHR) A0[idx] = 0u;
    for (int idx = tid; idx < BN * S1; idx += NTHR) A1[idx] = 0u;

    // xa[t][k][nl] = dinv-scaled aggregate (already scaled in k_pull)
    for (int idx = tid; idx < T_STEPS * 2 * BN; idx += NTHR) {
        int nl = idx & (BN - 1);
        int n = node0 + nl;
        if (n >= NN) n = NN - 1;
        xa[idx] = g_acc[n * 20 + (idx >> 6)];
    }
    __syncthreads();

    // ---- warp/lane geometry: 2 row-groups (32 nodes, 2 m-tiles) x 4 col-groups ----
    int w = tid >> 5;
    int l = tid & 31;
    int wr = w >> 2;                 // row group 0..1: nodes wr*32 .. wr*32+31
    int wc = w & 3;                  // col group: j in {wc, wc+4, wc+8, wc+12}
    int cb = 2 * (l & 3);
    int u0 = wc * 8 + cb;            // this thread's units u0, u0+1 (per gate type g)
    int rbase = wr * 32 + (l >> 2);  // node row base (+16*mt, +8*rho)

    float c0[8], c1[8];
#pragma unroll
    for (int i = 0; i < 8; i++) { c0[i] = 0.0f; c1[i] = 0.0f; }
    float obv = ob[0];

    for (int t = 0; t < T_STEPS; t++) {
        // ---- GCN ReLU features (tf32) into A0 cols 0..15 (256 thr: 4 feats each) ----
        {
            int nl = tid >> 2, f0 = (tid & 3) * 4;
            float x0v = xa[t * 2 * BN + nl];
            float x1v = xa[t * 2 * BN + BN + nl];
            uint32_t fv[4];
#pragma unroll
            for (int f = 0; f < 4; f++) {
                float v = fmaf(x0v, gws[(f0 + f) * 2],
                          fmaf(x1v, gws[(f0 + f) * 2 + 1], gbs[f0 + f]));
                fv[f] = tf32b(fmaxf(v, 0.0f));
            }
            *(uint4*)(A0 + nl * S0 + f0) = make_uint4(fv[0], fv[1], fv[2], fv[3]);
        }
        __syncthreads();   // B1: feats + h1(t-1) visible

        // ---- layer0 GEMM: 32 nodes x 32 gates per warp, K=48 ----
        // kk 0..1: feats from A0;  kk 2..5: h0(t-1) from A1 cols 0..31
        float d[2][4][4];
#pragma unroll
        for (int mt = 0; mt < 2; mt++)
#pragma unroll
            for (int g = 0; g < 4; g++) {
                float b0v = bs0[g * 32 + u0], b1v = bs0[g * 32 + u0 + 1];
                d[mt][g][0] = b0v; d[mt][g][1] = b1v; d[mt][g][2] = b0v; d[mt][g][3] = b1v;
            }
#pragma unroll
        for (int kk = 0; kk < 6; kk++) {
            uint32_t a0[2], a1[2], a2[2], a3[2];
#pragma unroll
            for (int mt = 0; mt < 2; mt++) {
                int row = rbase + mt * 16;
                int ab;
                const uint32_t* Ab;
                if (kk < 2) { Ab = A0; ab = row * S0 + kk * 8 + (l & 3); }
                else        { Ab = A1; ab = row * S1 + (kk - 2) * 8 + (l & 3); }
                int st = (kk < 2) ? S0 : S1;
                a0[mt] = Ab[ab];
                a1[mt] = Ab[ab + 8 * st];
                a2[mt] = Ab[ab + 4];
                a3[mt] = Ab[ab + 8 * st + 4];
            }
#pragma unroll
            for (int g = 0; g < 4; g++) {
                uint2 b = ((const uint2*)wf0)[(kk * 16 + wc + 4 * g) * 32 + l];
#pragma unroll
                for (int mt = 0; mt < 2; mt++)
                    mma_tf32(d[mt][g], a0[mt], a1[mt], a2[mt], a3[mt], b.x, b.y);
            }
        }
        __syncthreads();   // B2: all reads of h0(t-1) done

        // ---- layer0 activations (approx); h0 -> A1 cols 0..31 ----
#pragma unroll
        for (int mt = 0; mt < 2; mt++)
#pragma unroll
            for (int rho = 0; rho < 2; rho++)
#pragma unroll
                for (int p = 0; p < 2; p++) {
                    int q = 2 * rho + p;
                    int ci = (mt * 2 + rho) * 2 + p;
                    float gi = d[mt][0][q], gf = d[mt][1][q];
                    float gg = d[mt][2][q], go = d[mt][3][q];
                    float cc = sigf(gf) * c0[ci] + sigf(gi) * tanhap(gg);
                    c0[ci] = cc;
                    float h = sigf(go) * tanhap(cc);
                    int u = u0 + p;
                    int node = rbase + mt * 16 + 8 * rho;
                    A1[node * S1 + u] = tf32b(h);
                }
        __syncthreads();   // B3: new h0 visible

        // ---- layer1 GEMM: K=64 (h0 new cols 0..31 | h1 prev cols 32..63) ----
#pragma unroll
        for (int mt = 0; mt < 2; mt++)
#pragma unroll
            for (int g = 0; g < 4; g++) {
                float b0v = bs1[g * 32 + u0], b1v = bs1[g * 32 + u0 + 1];
                d[mt][g][0] = b0v; d[mt][g][1] = b1v; d[mt][g][2] = b0v; d[mt][g][3] = b1v;
            }
#pragma unroll
        for (int kk = 0; kk < 8; kk++) {
            uint32_t a0[2], a1[2], a2[2], a3[2];
#pragma unroll
            for (int mt = 0; mt < 2; mt++) {
                int ab = (rbase + mt * 16) * S1 + kk * 8 + (l & 3);
                a0[mt] = A1[ab];
                a1[mt] = A1[ab + 8 * S1];
                a2[mt] = A1[ab + 4];
                a3[mt] = A1[ab + 8 * S1 + 4];
            }
#pragma unroll
            for (int g = 0; g < 4; g++) {
                uint2 b = ((const uint2*)wf1)[(kk * 16 + wc + 4 * g) * 32 + l];
#pragma unroll
                for (int mt = 0; mt < 2; mt++)
                    mma_tf32(d[mt][g], a0[mt], a1[mt], a2[mt], a3[mt], b.x, b.y);
            }
        }
        __syncthreads();   // B4: all reads of h1(t-1) done

        // ---- layer1 activations (approx); h1 -> A1 cols 32..63; output partials ----
#pragma unroll
        for (int mt = 0; mt < 2; mt++)
#pragma unroll
            for (int rho = 0; rho < 2; rho++) {
                float po = 0.0f;
#pragma unroll
                for (int p = 0; p < 2; p++) {
                    int q = 2 * rho + p;
                    int ci = (mt * 2 + rho) * 2 + p;
                    float gi = d[mt][0][q], gf = d[mt][1][q];
                    float gg = d[mt][2][q], go = d[mt][3][q];
                    float cc = sigf(gf) * c1[ci] + sigf(gi) * tanhap(gg);
                    c1[ci] = cc;
                    float h = sigf(go) * tanhap(cc);
                    int u = u0 + p;
                    int node = rbase + mt * 16 + 8 * rho;
                    A1[node * S1 + 32 + u] = tf32b(h);
                    po = fmaf(h, ows[u], po);
                }
                // sum over the 4 lanes sharing this node (units wc*8..wc*8+7)
                po += __shfl_xor_sync(0xFFFFFFFFu, po, 1);
                po += __shfl_xor_sync(0xFFFFFFFFu, po, 2);
                if ((l & 3) == 0) {
                    int node = rbase + mt * 16 + 8 * rho;
                    outp[node * 4 + wc] = po;
                }
            }
        __syncthreads();   // B5

        if (tid < BN) {
            int n = node0 + tid;
            if (n < NN) {
                out[t * NN + n] = obv + outp[tid * 4] + outp[tid * 4 + 1]
                                      + outp[tid * 4 + 2] + outp[tid * 4 + 3];
            }
        }
        // outp reads finish before next t's B4 rewrites; A-buffer reuse guarded by B1/B2
    }
}

// ---------------- launcher ----------------
extern "C" void kernel_launch(void* const* d_in, const int* in_sizes, int n_in,
                              void* d_out, int out_size) {
    const float* x    = (const float*)d_in[0];
    const int*   ei   = (const int*)  d_in[1];
    const float* gw   = (const float*)d_in[2];
    const float* gb   = (const float*)d_in[3];
    const float* wih0 = (const float*)d_in[4];
    const float* whh0 = (const float*)d_in[5];
    const float* bih0 = (const float*)d_in[6];
    const float* bhh0 = (const float*)d_in[7];
    const float* wih1 = (const float*)d_in[8];
    const float* whh1 = (const float*)d_in[9];
    const float* bih1 = (const float*)d_in[10];
    const float* bhh1 = (const float*)d_in[11];
    const float* ow   = (const float*)d_in[12];
    const float* ob   = (const float*)d_in[13];
    float* out = (float*)d_out;

    cudaFuncSetAttribute(k_main, cudaFuncAttributeMaxDynamicSharedMemorySize, SM_BYTES);

    k_init     <<<(NN + 255) / 256, 256>>>();
    k_count    <<<(NE + 255) / 256, 256>>>(ei);
    k_scan_part<<<NB_SCAN, 256>>>();
    k_xs       <<<(T_STEPS * NN * 2 + 255) / 256, 256>>>(x);
    k_scan_top <<<1, 256>>>();
    k_fill     <<<(NE + 255) / 256, 256>>>(ei);
    k_pull     <<<(NN * 32 + 255) / 256, 256>>>();
    k_main     <<<(NN + BN - 1) / BN, NTHR, SM_BYTES>>>(
        wih0, whh0, bih0, bhh0, wih1, whh1, bih1, bhh1, gw, gb, ow, ob, out);
}